// round 2
// baseline (speedup 1.0000x reference)
#include <cuda_runtime.h>

#define N_NODES 50000
#define D 128
#define N_EDGES_MAX 800000
#define SCAN_THREADS 1024

// ---------------------------------------------------------------------------
// Device scratch (no allocations allowed in kernel_launch)
// ---------------------------------------------------------------------------
__device__ float g_h[(size_t)N_NODES * D];     // aggregated features
__device__ int   g_cnt[N_NODES];               // per-dst degree
__device__ int   g_off[N_NODES + 1];           // CSR offsets
__device__ int   g_cur[N_NODES];               // placement cursors
__device__ int   g_srcs[N_EDGES_MAX];          // src ids bucketed by dst

// ---------------------------------------------------------------------------
// Kernel 1: zero the degree counters
// ---------------------------------------------------------------------------
__global__ void zero_cnt_kernel() {
    int i = blockIdx.x * blockDim.x + threadIdx.x;
    if (i < N_NODES) g_cnt[i] = 0;
}

// ---------------------------------------------------------------------------
// Kernel 2: histogram of dst
// ---------------------------------------------------------------------------
__global__ void hist_kernel(const int* __restrict__ dst, int n_edges) {
    int e = blockIdx.x * blockDim.x + threadIdx.x;
    if (e < n_edges) atomicAdd(&g_cnt[dst[e]], 1);
}

// ---------------------------------------------------------------------------
// Kernel 3: single-block exclusive scan of g_cnt -> g_off; zero cursors.
// 1024 threads, each owns a contiguous chunk of ~49 counters.
// ---------------------------------------------------------------------------
__global__ __launch_bounds__(SCAN_THREADS) void scan_kernel() {
    __shared__ int sums[SCAN_THREADS];
    const int ITEMS = (N_NODES + SCAN_THREADS - 1) / SCAN_THREADS;  // 49
    int t = threadIdx.x;
    int start = t * ITEMS;
    int end = min(start + ITEMS, N_NODES);

    int s = 0;
    for (int i = start; i < end; i++) s += g_cnt[i];
    sums[t] = s;
    __syncthreads();

    // Hillis-Steele inclusive scan over the 1024 chunk sums
    for (int off = 1; off < SCAN_THREADS; off <<= 1) {
        int v = (t >= off) ? sums[t - off] : 0;
        __syncthreads();
        sums[t] += v;
        __syncthreads();
    }

    int run = (t == 0) ? 0 : sums[t - 1];  // exclusive prefix of this chunk
    for (int i = start; i < end; i++) {
        int c = g_cnt[i];
        g_off[i] = run;
        g_cur[i] = 0;
        run += c;
    }
    if (t == SCAN_THREADS - 1) g_off[N_NODES] = run;  // = n_edges
}

// ---------------------------------------------------------------------------
// Kernel 4: bucket placement — scatter src ids into CSR buckets
// ---------------------------------------------------------------------------
__global__ void place_kernel(const int* __restrict__ src,
                             const int* __restrict__ dst, int n_edges) {
    int e = blockIdx.x * blockDim.x + threadIdx.x;
    if (e < n_edges) {
        int d = dst[e];
        int pos = g_off[d] + atomicAdd(&g_cur[d], 1);
        g_srcs[pos] = src[e];
    }
}

// ---------------------------------------------------------------------------
// Kernel 5: gather-reduce — one warp per node.
// Each lane accumulates a float4 slice of the 128-float row in registers,
// then one clean 16B store. No atomics.
// ---------------------------------------------------------------------------
__global__ void gather_kernel(const float* __restrict__ x) {
    int gw = (blockIdx.x * blockDim.x + threadIdx.x) >> 5;  // node id
    int lane = threadIdx.x & 31;
    if (gw >= N_NODES) return;

    int beg = g_off[gw];
    int end = g_off[gw + 1];

    float4 acc = make_float4(0.f, 0.f, 0.f, 0.f);
    int e = beg;

    // unroll x4 for MLP
    for (; e + 3 < end; e += 4) {
        int s0 = __ldg(&g_srcs[e + 0]);
        int s1 = __ldg(&g_srcs[e + 1]);
        int s2 = __ldg(&g_srcs[e + 2]);
        int s3 = __ldg(&g_srcs[e + 3]);
        float4 v0 = __ldg(reinterpret_cast<const float4*>(x + (size_t)s0 * D) + lane);
        float4 v1 = __ldg(reinterpret_cast<const float4*>(x + (size_t)s1 * D) + lane);
        float4 v2 = __ldg(reinterpret_cast<const float4*>(x + (size_t)s2 * D) + lane);
        float4 v3 = __ldg(reinterpret_cast<const float4*>(x + (size_t)s3 * D) + lane);
        acc.x += v0.x + v1.x + v2.x + v3.x;
        acc.y += v0.y + v1.y + v2.y + v3.y;
        acc.z += v0.z + v1.z + v2.z + v3.z;
        acc.w += v0.w + v1.w + v2.w + v3.w;
    }
    for (; e < end; e++) {
        int s0 = __ldg(&g_srcs[e]);
        float4 v0 = __ldg(reinterpret_cast<const float4*>(x + (size_t)s0 * D) + lane);
        acc.x += v0.x; acc.y += v0.y; acc.z += v0.z; acc.w += v0.w;
    }

    reinterpret_cast<float4*>(g_h + (size_t)gw * D)[lane] = acc;
}

// ---------------------------------------------------------------------------
// Kernel 6: out = h @ W^T + b
// Tiled SGEMM: BM=128, BN=128, BK=16, 256 threads, 8x8 per thread.
// ---------------------------------------------------------------------------
__global__ __launch_bounds__(256) void gemm_bias_kernel(
    const float* __restrict__ W,
    const float* __restrict__ b,
    float* __restrict__ out) {

    __shared__ float As[16][128];  // As[k][row]
    __shared__ float Bs[16][128];  // Bs[k][o] = W[o][k]

    const int tid = threadIdx.x;
    const int tx = tid & 15;
    const int ty = tid >> 4;
    const int row0 = blockIdx.x * 128;

    float acc[8][8];
#pragma unroll
    for (int i = 0; i < 8; i++)
#pragma unroll
        for (int j = 0; j < 8; j++) acc[i][j] = 0.f;

    for (int k0 = 0; k0 < 128; k0 += 16) {
#pragma unroll
        for (int t = 0; t < 2; t++) {
            int fid = tid * 2 + t;
            int r = fid >> 2;
            int kc = (fid & 3) * 4;
            int row = row0 + r;
            float4 v = make_float4(0.f, 0.f, 0.f, 0.f);
            if (row < N_NODES)
                v = *reinterpret_cast<const float4*>(g_h + (size_t)row * D + k0 + kc);
            As[kc + 0][r] = v.x;
            As[kc + 1][r] = v.y;
            As[kc + 2][r] = v.z;
            As[kc + 3][r] = v.w;
        }
#pragma unroll
        for (int t = 0; t < 2; t++) {
            int fid = tid * 2 + t;
            int o = fid >> 2;
            int kc = (fid & 3) * 4;
            float4 v = *reinterpret_cast<const float4*>(W + (size_t)o * D + k0 + kc);
            Bs[kc + 0][o] = v.x;
            Bs[kc + 1][o] = v.y;
            Bs[kc + 2][o] = v.z;
            Bs[kc + 3][o] = v.w;
        }
        __syncthreads();

#pragma unroll
        for (int kk = 0; kk < 16; kk++) {
            float ra[8], rb[8];
#pragma unroll
            for (int i = 0; i < 8; i++) ra[i] = As[kk][ty * 8 + i];
#pragma unroll
            for (int j = 0; j < 8; j++) rb[j] = Bs[kk][tx * 8 + j];
#pragma unroll
            for (int i = 0; i < 8; i++)
#pragma unroll
                for (int j = 0; j < 8; j++)
                    acc[i][j] += ra[i] * rb[j];
        }
        __syncthreads();
    }

#pragma unroll
    for (int i = 0; i < 8; i++) {
        int row = row0 + ty * 8 + i;
        if (row >= N_NODES) continue;
#pragma unroll
        for (int j = 0; j < 8; j += 4) {
            int col = tx * 8 + j;
            float4 v;
            v.x = acc[i][j + 0] + __ldg(b + col + 0);
            v.y = acc[i][j + 1] + __ldg(b + col + 1);
            v.z = acc[i][j + 2] + __ldg(b + col + 2);
            v.w = acc[i][j + 3] + __ldg(b + col + 3);
            *reinterpret_cast<float4*>(out + (size_t)row * D + col) = v;
        }
    }
}

// ---------------------------------------------------------------------------
// Launch: inputs in metadata order: x, src, dst, W, b
// ---------------------------------------------------------------------------
extern "C" void kernel_launch(void* const* d_in, const int* in_sizes, int n_in,
                              void* d_out, int out_size) {
    const float* x   = (const float*)d_in[0];
    const int*   src = (const int*)d_in[1];
    const int*   dst = (const int*)d_in[2];
    const float* W   = (const float*)d_in[3];
    const float* b   = (const float*)d_in[4];
    float* out = (float*)d_out;

    const int n_edges = in_sizes[1];

    // 1) zero degree counters
    zero_cnt_kernel<<<(N_NODES + 255) / 256, 256>>>();
    // 2) histogram over dst
    hist_kernel<<<(n_edges + 255) / 256, 256>>>(dst, n_edges);
    // 3) exclusive scan -> CSR offsets (+ cursor reset)
    scan_kernel<<<1, SCAN_THREADS>>>();
    // 4) bucket placement of src ids
    place_kernel<<<(n_edges + 255) / 256, 256>>>(src, dst, n_edges);
    // 5) gather-reduce per node (no atomics)
    {
        long long total_threads = (long long)N_NODES * 32;
        int blocks = (int)((total_threads + 255) / 256);
        gather_kernel<<<blocks, 256>>>(x);
    }
    // 6) GEMM + bias
    gemm_bias_kernel<<<(N_NODES + 127) / 128, 256>>>(W, b, out);
}

// round 4
// speedup vs baseline: 1.3033x; 1.3033x over previous
#include <cuda_runtime.h>
#include <cstdint>

#define N_NODES 50000
#define D 128
#define N_TILES ((N_NODES + 127) / 128)   // 391

// ---------------------------------------------------------------------------
// Device scratch
// ---------------------------------------------------------------------------
__device__ float g_h[(size_t)N_NODES * D];
// W packed in mma.sync B-fragment order:
// [ntile(16)][kstep(16)][lane(32)] x float4 {bhi0, bhi1, blo0, blo1}
__device__ float4 g_Wpack[16 * 16 * 32];

// ---------------------------------------------------------------------------
// tf32 helpers (plain sm_103 ISA — no 'a' features)
// ---------------------------------------------------------------------------
__device__ __forceinline__ uint32_t f32_to_tf32(float v) {
    uint32_t r;
    asm("cvt.rna.tf32.f32 %0, %1;" : "=r"(r) : "f"(v));
    return r;
}

__device__ __forceinline__ void mma_tf32(float* acc, const uint32_t* a,
                                         uint32_t b0, uint32_t b1) {
    asm volatile(
        "mma.sync.aligned.m16n8k8.row.col.f32.tf32.tf32.f32 "
        "{%0,%1,%2,%3}, {%4,%5,%6,%7}, {%8,%9}, {%0,%1,%2,%3};"
        : "+f"(acc[0]), "+f"(acc[1]), "+f"(acc[2]), "+f"(acc[3])
        : "r"(a[0]), "r"(a[1]), "r"(a[2]), "r"(a[3]), "r"(b0), "r"(b1));
}

// ---------------------------------------------------------------------------
// Kernel 1: zero accumulator
// ---------------------------------------------------------------------------
__global__ void zero_h_kernel() {
    int i = blockIdx.x * blockDim.x + threadIdx.x;
    const int n4 = N_NODES * D / 4;
    if (i < n4) reinterpret_cast<float4*>(g_h)[i] = make_float4(0.f, 0.f, 0.f, 0.f);
}

// ---------------------------------------------------------------------------
// Kernel 2: pack W into tf32 hi/lo B fragments.
// B[k][n] = W[n][k] (out = h @ W^T). For ntile t, kstep j, lane l:
//   n = t*8 + l/4, k0 = j*8 + l%4, k1 = k0 + 4
// ---------------------------------------------------------------------------
__global__ void pack_W_kernel(const float* __restrict__ W) {
    int idx = blockIdx.x * blockDim.x + threadIdx.x;   // 0..8191
    if (idx >= 16 * 16 * 32) return;
    int lane = idx & 31;
    int j = (idx >> 5) & 15;
    int t = idx >> 9;
    int n = t * 8 + (lane >> 2);
    int k0 = j * 8 + (lane & 3);

    float w0 = __ldg(W + n * D + k0);
    float w1 = __ldg(W + n * D + k0 + 4);
    uint32_t h0 = f32_to_tf32(w0);
    uint32_t h1 = f32_to_tf32(w1);
    uint32_t l0 = f32_to_tf32(w0 - __uint_as_float(h0));
    uint32_t l1 = f32_to_tf32(w1 - __uint_as_float(h1));

    float4 v;
    v.x = __uint_as_float(h0);
    v.y = __uint_as_float(h1);
    v.z = __uint_as_float(l0);
    v.w = __uint_as_float(l1);
    g_Wpack[idx] = v;
}

// ---------------------------------------------------------------------------
// Kernel 3: edge scatter — one warp per edge, red.global.add.v4.f32
// ---------------------------------------------------------------------------
__global__ void scatter_edges_kernel(const float* __restrict__ x,
                                     const int* __restrict__ src,
                                     const int* __restrict__ dst,
                                     int n_edges) {
    int gw = (blockIdx.x * blockDim.x + threadIdx.x) >> 5;
    int lane = threadIdx.x & 31;
    if (gw >= n_edges) return;

    int s = __ldg(src + gw);
    int d = __ldg(dst + gw);

    float4 v = __ldg(reinterpret_cast<const float4*>(x + (size_t)s * D) + lane);

    float* hp = g_h + (size_t)d * D + lane * 4;
    asm volatile("red.global.add.v4.f32 [%0], {%1, %2, %3, %4};"
                 :: "l"(hp), "f"(v.x), "f"(v.y), "f"(v.z), "f"(v.w)
                 : "memory");
}

// ---------------------------------------------------------------------------
// Kernel 4: out = h @ W^T + b via mma.sync tf32x3.
// One warp per 16 rows, full 128 output cols in registers (16 n-tiles x 4).
// B fragments come straight from g_Wpack with single ldg.128 (L1-resident).
// No smem, no syncs.
// ---------------------------------------------------------------------------
__global__ __launch_bounds__(256) void gemm_mma_kernel(
    const float* __restrict__ bias,
    float* __restrict__ out) {

    const int wid = threadIdx.x >> 5;
    const int lane = threadIdx.x & 31;
    const int r0 = blockIdx.x * 128 + wid * 16;

    const int rowA0 = r0 + (lane >> 2);
    const int rowA1 = rowA0 + 8;
    // clamp for safe loads; stores are guarded
    const int rc0 = rowA0 < N_NODES ? rowA0 : N_NODES - 1;
    const int rc1 = rowA1 < N_NODES ? rowA1 : N_NODES - 1;
    const float* hp0 = g_h + (size_t)rc0 * D;
    const float* hp1 = g_h + (size_t)rc1 * D;

    float acc[16][4];
#pragma unroll
    for (int t = 0; t < 16; t++)
#pragma unroll
        for (int q = 0; q < 4; q++) acc[t][q] = 0.f;

#pragma unroll
    for (int j = 0; j < 16; j++) {
        const int kc = j * 8 + (lane & 3);
        // A fragment (m16k8, row-major)
        float a0 = __ldg(hp0 + kc);
        float a1 = __ldg(hp1 + kc);
        float a2 = __ldg(hp0 + kc + 4);
        float a3 = __ldg(hp1 + kc + 4);

        uint32_t ah[4], al[4];
        ah[0] = f32_to_tf32(a0); al[0] = f32_to_tf32(a0 - __uint_as_float(ah[0]));
        ah[1] = f32_to_tf32(a1); al[1] = f32_to_tf32(a1 - __uint_as_float(ah[1]));
        ah[2] = f32_to_tf32(a2); al[2] = f32_to_tf32(a2 - __uint_as_float(ah[2]));
        ah[3] = f32_to_tf32(a3); al[3] = f32_to_tf32(a3 - __uint_as_float(ah[3]));

        const float4* wp = g_Wpack + j * 32 + lane;
#pragma unroll
        for (int t = 0; t < 16; t++) {
            float4 bf = __ldg(wp + t * 512);   // [t][j][lane]
            uint32_t bh0 = __float_as_uint(bf.x);
            uint32_t bh1 = __float_as_uint(bf.y);
            uint32_t bl0 = __float_as_uint(bf.z);
            uint32_t bl1 = __float_as_uint(bf.w);
            mma_tf32(acc[t], ah, bh0, bh1);   // Ah*Bh
            mma_tf32(acc[t], ah, bl0, bl1);   // Ah*Bl
            mma_tf32(acc[t], al, bh0, bh1);   // Al*Bh
        }
    }

    // epilogue: c0/c1 -> rowA0 cols (col, col+1); c2/c3 -> rowA1
#pragma unroll
    for (int t = 0; t < 16; t++) {
        int col = t * 8 + (lane & 3) * 2;
        float b0 = __ldg(bias + col);
        float b1 = __ldg(bias + col + 1);
        if (rowA0 < N_NODES) {
            float2 v = make_float2(acc[t][0] + b0, acc[t][1] + b1);
            *reinterpret_cast<float2*>(out + (size_t)rowA0 * D + col) = v;
        }
        if (rowA1 < N_NODES) {
            float2 v = make_float2(acc[t][2] + b0, acc[t][3] + b1);
            *reinterpret_cast<float2*>(out + (size_t)rowA1 * D + col) = v;
        }
    }
}

// ---------------------------------------------------------------------------
// Launch: inputs in metadata order: x, src, dst, W, b
// ---------------------------------------------------------------------------
extern "C" void kernel_launch(void* const* d_in, const int* in_sizes, int n_in,
                              void* d_out, int out_size) {
    const float* x   = (const float*)d_in[0];
    const int*   src = (const int*)d_in[1];
    const int*   dst = (const int*)d_in[2];
    const float* W   = (const float*)d_in[3];
    const float* b   = (const float*)d_in[4];
    float* out = (float*)d_out;

    const int n_edges = in_sizes[1];

    // 1) zero accumulator
    {
        int n4 = N_NODES * D / 4;
        zero_h_kernel<<<(n4 + 255) / 256, 256>>>();
    }
    // 2) pack W into tf32 hi/lo fragments (independent of scatter)
    pack_W_kernel<<<32, 256>>>(W);
    // 3) scatter-add edges (one warp per edge)
    {
        long long total_threads = (long long)n_edges * 32;
        int blocks = (int)((total_threads + 255) / 256);
        scatter_edges_kernel<<<blocks, 256>>>(x, src, dst, n_edges);
    }
    // 4) tensor-core GEMM + bias (tf32x3)
    gemm_mma_kernel<<<N_TILES, 256>>>(b, out);
}

// round 5
// speedup vs baseline: 1.4034x; 1.0768x over previous
#include <cuda_runtime.h>
#include <cstdint>

#define N_NODES 50000
#define D 128
#define N_TILES ((N_NODES + 127) / 128)   // 391

// ---------------------------------------------------------------------------
// Device scratch
// ---------------------------------------------------------------------------
__device__ float g_h[(size_t)N_NODES * D];
// W packed in mma.sync B-fragment order:
// [ntile(16)][kstep(16)][lane(32)] x float4 {bhi0, bhi1, blo0, blo1}
__device__ float4 g_Wpack[16 * 16 * 32];

// ---------------------------------------------------------------------------
// tf32 helpers (plain sm_103 ISA — no 'a' features)
// ---------------------------------------------------------------------------
__device__ __forceinline__ uint32_t f32_to_tf32(float v) {
    uint32_t r;
    asm("cvt.rna.tf32.f32 %0, %1;" : "=r"(r) : "f"(v));
    return r;
}

__device__ __forceinline__ void mma_tf32(float* acc, const uint32_t* a,
                                         uint32_t b0, uint32_t b1) {
    asm volatile(
        "mma.sync.aligned.m16n8k8.row.col.f32.tf32.tf32.f32 "
        "{%0,%1,%2,%3}, {%4,%5,%6,%7}, {%8,%9}, {%0,%1,%2,%3};"
        : "+f"(acc[0]), "+f"(acc[1]), "+f"(acc[2]), "+f"(acc[3])
        : "r"(a[0]), "r"(a[1]), "r"(a[2]), "r"(a[3]), "r"(b0), "r"(b1));
}

// ---------------------------------------------------------------------------
// Kernel 1: zero accumulator
// ---------------------------------------------------------------------------
__global__ void zero_h_kernel() {
    int i = blockIdx.x * blockDim.x + threadIdx.x;
    const int n4 = N_NODES * D / 4;
    if (i < n4) reinterpret_cast<float4*>(g_h)[i] = make_float4(0.f, 0.f, 0.f, 0.f);
}

// ---------------------------------------------------------------------------
// Kernel 2: pack W into tf32 hi/lo B fragments.
// B[k][n] = W[n][k] (out = h @ W^T). For ntile t, kstep j, lane l:
//   n = t*8 + l/4, k0 = j*8 + l%4, k1 = k0 + 4
// ---------------------------------------------------------------------------
__global__ void pack_W_kernel(const float* __restrict__ W) {
    int idx = blockIdx.x * blockDim.x + threadIdx.x;   // 0..8191
    if (idx >= 16 * 16 * 32) return;
    int lane = idx & 31;
    int j = (idx >> 5) & 15;
    int t = idx >> 9;
    int n = t * 8 + (lane >> 2);
    int k0 = j * 8 + (lane & 3);

    float w0 = __ldg(W + n * D + k0);
    float w1 = __ldg(W + n * D + k0 + 4);
    uint32_t h0 = f32_to_tf32(w0);
    uint32_t h1 = f32_to_tf32(w1);
    uint32_t l0 = f32_to_tf32(w0 - __uint_as_float(h0));
    uint32_t l1 = f32_to_tf32(w1 - __uint_as_float(h1));

    float4 v;
    v.x = __uint_as_float(h0);
    v.y = __uint_as_float(h1);
    v.z = __uint_as_float(l0);
    v.w = __uint_as_float(l1);
    g_Wpack[idx] = v;
}

// ---------------------------------------------------------------------------
// Kernel 3: edge scatter — one warp per edge, red.global.add.v4.f32
// (measured at the LTS throughput floor; do not touch)
// ---------------------------------------------------------------------------
__global__ void scatter_edges_kernel(const float* __restrict__ x,
                                     const int* __restrict__ src,
                                     const int* __restrict__ dst,
                                     int n_edges) {
    int gw = (blockIdx.x * blockDim.x + threadIdx.x) >> 5;
    int lane = threadIdx.x & 31;
    if (gw >= n_edges) return;

    int s = __ldg(src + gw);
    int d = __ldg(dst + gw);

    float4 v = __ldg(reinterpret_cast<const float4*>(x + (size_t)s * D) + lane);

    float* hp = g_h + (size_t)d * D + lane * 4;
    asm volatile("red.global.add.v4.f32 [%0], {%1, %2, %3, %4};"
                 :: "l"(hp), "f"(v.x), "f"(v.y), "f"(v.z), "f"(v.w)
                 : "memory");
}

// ---------------------------------------------------------------------------
// Kernel 4: out = h @ W^T + b via mma.sync tf32x3.
// Column-split: one warp per 16 rows x 64 cols (8 n-tiles, acc = 32 regs).
// blockIdx.x = row tile (128 rows / 8 warps), blockIdx.y = column half.
// B fragments from g_Wpack via single ldg.128 (L1-resident, 128KB total).
// No smem, no syncs.
// ---------------------------------------------------------------------------
__global__ __launch_bounds__(256, 2) void gemm_mma_kernel(
    const float* __restrict__ bias,
    float* __restrict__ out) {

    const int wid = threadIdx.x >> 5;
    const int lane = threadIdx.x & 31;
    const int r0 = blockIdx.x * 128 + wid * 16;
    const int half = blockIdx.y;            // 0 or 1: cols [0,64) or [64,128)

    const int rowA0 = r0 + (lane >> 2);
    const int rowA1 = rowA0 + 8;
    const int rc0 = rowA0 < N_NODES ? rowA0 : N_NODES - 1;
    const int rc1 = rowA1 < N_NODES ? rowA1 : N_NODES - 1;
    const float* hp0 = g_h + (size_t)rc0 * D;
    const float* hp1 = g_h + (size_t)rc1 * D;

    float acc[8][4];
#pragma unroll
    for (int t = 0; t < 8; t++)
#pragma unroll
        for (int q = 0; q < 4; q++) acc[t][q] = 0.f;

#pragma unroll 4
    for (int j = 0; j < 16; j++) {
        const int kc = j * 8 + (lane & 3);
        float a0 = __ldg(hp0 + kc);
        float a1 = __ldg(hp1 + kc);
        float a2 = __ldg(hp0 + kc + 4);
        float a3 = __ldg(hp1 + kc + 4);

        uint32_t ah[4], al[4];
        ah[0] = f32_to_tf32(a0); al[0] = f32_to_tf32(a0 - __uint_as_float(ah[0]));
        ah[1] = f32_to_tf32(a1); al[1] = f32_to_tf32(a1 - __uint_as_float(ah[1]));
        ah[2] = f32_to_tf32(a2); al[2] = f32_to_tf32(a2 - __uint_as_float(ah[2]));
        ah[3] = f32_to_tf32(a3); al[3] = f32_to_tf32(a3 - __uint_as_float(ah[3]));

        const float4* wp = g_Wpack + (size_t)(half * 8) * 512 + j * 32 + lane;
#pragma unroll
        for (int t = 0; t < 8; t++) {
            float4 bf = __ldg(wp + t * 512);   // [half*8 + t][j][lane]
            uint32_t bh0 = __float_as_uint(bf.x);
            uint32_t bh1 = __float_as_uint(bf.y);
            uint32_t bl0 = __float_as_uint(bf.z);
            uint32_t bl1 = __float_as_uint(bf.w);
            mma_tf32(acc[t], ah, bh0, bh1);   // Ah*Bh
            mma_tf32(acc[t], ah, bl0, bl1);   // Ah*Bl
            mma_tf32(acc[t], al, bh0, bh1);   // Al*Bh
        }
    }

    // epilogue
#pragma unroll
    for (int t = 0; t < 8; t++) {
        int col = half * 64 + t * 8 + (lane & 3) * 2;
        float b0 = __ldg(bias + col);
        float b1 = __ldg(bias + col + 1);
        if (rowA0 < N_NODES) {
            float2 v = make_float2(acc[t][0] + b0, acc[t][1] + b1);
            *reinterpret_cast<float2*>(out + (size_t)rowA0 * D + col) = v;
        }
        if (rowA1 < N_NODES) {
            float2 v = make_float2(acc[t][2] + b0, acc[t][3] + b1);
            *reinterpret_cast<float2*>(out + (size_t)rowA1 * D + col) = v;
        }
    }
}

// ---------------------------------------------------------------------------
// Launch: inputs in metadata order: x, src, dst, W, b
// ---------------------------------------------------------------------------
extern "C" void kernel_launch(void* const* d_in, const int* in_sizes, int n_in,
                              void* d_out, int out_size) {
    const float* x   = (const float*)d_in[0];
    const int*   src = (const int*)d_in[1];
    const int*   dst = (const int*)d_in[2];
    const float* W   = (const float*)d_in[3];
    const float* b   = (const float*)d_in[4];
    float* out = (float*)d_out;

    const int n_edges = in_sizes[1];

    // 1) zero accumulator
    {
        int n4 = N_NODES * D / 4;
        zero_h_kernel<<<(n4 + 255) / 256, 256>>>();
    }
    // 2) pack W into tf32 hi/lo fragments
    pack_W_kernel<<<32, 256>>>(W);
    // 3) scatter-add edges (one warp per edge)
    {
        long long total_threads = (long long)n_edges * 32;
        int blocks = (int)((total_threads + 255) / 256);
        scatter_edges_kernel<<<blocks, 256>>>(x, src, dst, n_edges);
    }
    // 4) tensor-core GEMM + bias (tf32x3), column-split for occupancy
    {
        dim3 grid(N_TILES, 2);
        gemm_mma_kernel<<<grid, 256>>>(b, out);
    }
}

// round 6
// speedup vs baseline: 1.4037x; 1.0003x over previous
#include <cuda_runtime.h>
#include <cstdint>

#define N_NODES 50000
#define D 128
#define N_TILES ((N_NODES + 127) / 128)   // 391
#define ZERO_BLOCKS ((N_NODES * D / 4 + 255) / 256)   // 6250
#define PACK_BLOCKS 32                                // 8192 threads

// ---------------------------------------------------------------------------
// Device scratch
// ---------------------------------------------------------------------------
__device__ float g_h[(size_t)N_NODES * D];
// W packed in mma.sync B-fragment order:
// [ntile(16)][kstep(16)][lane(32)] x float4 {bhi0, bhi1, blo0, blo1}
__device__ float4 g_Wpack[16 * 16 * 32];

// ---------------------------------------------------------------------------
// tf32 helpers (plain sm_103 ISA — no 'a' features)
// ---------------------------------------------------------------------------
__device__ __forceinline__ uint32_t f32_to_tf32(float v) {
    uint32_t r;
    asm("cvt.rna.tf32.f32 %0, %1;" : "=r"(r) : "f"(v));
    return r;
}

__device__ __forceinline__ void mma_tf32(float* acc, const uint32_t* a,
                                         uint32_t b0, uint32_t b1) {
    asm volatile(
        "mma.sync.aligned.m16n8k8.row.col.f32.tf32.tf32.f32 "
        "{%0,%1,%2,%3}, {%4,%5,%6,%7}, {%8,%9}, {%0,%1,%2,%3};"
        : "+f"(acc[0]), "+f"(acc[1]), "+f"(acc[2]), "+f"(acc[3])
        : "r"(a[0]), "r"(a[1]), "r"(a[2]), "r"(a[3]), "r"(b0), "r"(b1));
}

// ---------------------------------------------------------------------------
// Kernel 1: fused init — zero g_h AND pack W into tf32 hi/lo B fragments.
// Blocks [0, ZERO_BLOCKS) zero; blocks [ZERO_BLOCKS, +PACK_BLOCKS) pack.
// ---------------------------------------------------------------------------
__global__ void init_kernel(const float* __restrict__ W) {
    int bid = blockIdx.x;
    if (bid < ZERO_BLOCKS) {
        int i = bid * 256 + threadIdx.x;
        const int n4 = N_NODES * D / 4;
        if (i < n4) reinterpret_cast<float4*>(g_h)[i] = make_float4(0.f, 0.f, 0.f, 0.f);
        return;
    }
    int idx = (bid - ZERO_BLOCKS) * 256 + threadIdx.x;   // 0..8191
    if (idx >= 16 * 16 * 32) return;
    int lane = idx & 31;
    int j = (idx >> 5) & 15;
    int t = idx >> 9;
    int n = t * 8 + (lane >> 2);
    int k0 = j * 8 + (lane & 3);

    float w0 = __ldg(W + n * D + k0);
    float w1 = __ldg(W + n * D + k0 + 4);
    uint32_t h0 = f32_to_tf32(w0);
    uint32_t h1 = f32_to_tf32(w1);
    uint32_t l0 = f32_to_tf32(w0 - __uint_as_float(h0));
    uint32_t l1 = f32_to_tf32(w1 - __uint_as_float(h1));

    float4 v;
    v.x = __uint_as_float(h0);
    v.y = __uint_as_float(h1);
    v.z = __uint_as_float(l0);
    v.w = __uint_as_float(l1);
    g_Wpack[idx] = v;
}

// ---------------------------------------------------------------------------
// Kernel 2: edge scatter — one warp per edge, red.global.add.v4.f32
// (measured at the REDG/LTS floor; leave alone)
// ---------------------------------------------------------------------------
__global__ void scatter_edges_kernel(const float* __restrict__ x,
                                     const int* __restrict__ src,
                                     const int* __restrict__ dst,
                                     int n_edges) {
    int gw = (blockIdx.x * blockDim.x + threadIdx.x) >> 5;
    int lane = threadIdx.x & 31;
    if (gw >= n_edges) return;

    int s = __ldg(src + gw);
    int d = __ldg(dst + gw);

    float4 v = __ldg(reinterpret_cast<const float4*>(x + (size_t)s * D) + lane);

    float* hp = g_h + (size_t)d * D + lane * 4;
    asm volatile("red.global.add.v4.f32 [%0], {%1, %2, %3, %4};"
                 :: "l"(hp), "f"(v.x), "f"(v.y), "f"(v.z), "f"(v.w)
                 : "memory");
}

// ---------------------------------------------------------------------------
// Kernel 3: out = h @ W^T + b via mma.sync tf32x3.
// One warp per 16 rows x 64 cols; blockIdx.y selects column half.
// B fragments staged ONCE per block in 64KB smem (kills 8x duplicated
// LDG.128 traffic through L1); A loaded from L2/L1-hot g_h.
// ---------------------------------------------------------------------------
#define SB_ELEMS (8 * 16 * 32)             // 4096 float4 = 64KB

__global__ __launch_bounds__(256, 2) void gemm_mma_kernel(
    const float* __restrict__ bias,
    float* __restrict__ out) {

    extern __shared__ float4 sB[];         // [t(8)][j(16)][lane(32)]

    const int tid = threadIdx.x;
    const int wid = tid >> 5;
    const int lane = tid & 31;
    const int half = blockIdx.y;           // 0 or 1: cols [0,64) or [64,128)

    // cooperative copy of this half's B fragments (contiguous 64KB)
    {
        const float4* wsrc = g_Wpack + half * SB_ELEMS;
#pragma unroll
        for (int i = 0; i < SB_ELEMS / 256; i++)
            sB[i * 256 + tid] = __ldg(wsrc + i * 256 + tid);
    }

    const int r0 = blockIdx.x * 128 + wid * 16;
    const int rowA0 = r0 + (lane >> 2);
    const int rowA1 = rowA0 + 8;
    const int rc0 = rowA0 < N_NODES ? rowA0 : N_NODES - 1;
    const int rc1 = rowA1 < N_NODES ? rowA1 : N_NODES - 1;
    const float* hp0 = g_h + (size_t)rc0 * D;
    const float* hp1 = g_h + (size_t)rc1 * D;

    float acc[8][4];
#pragma unroll
    for (int t = 0; t < 8; t++)
#pragma unroll
        for (int q = 0; q < 4; q++) acc[t][q] = 0.f;

    __syncthreads();

#pragma unroll 4
    for (int j = 0; j < 16; j++) {
        const int kc = j * 8 + (lane & 3);
        float a0 = __ldg(hp0 + kc);
        float a1 = __ldg(hp1 + kc);
        float a2 = __ldg(hp0 + kc + 4);
        float a3 = __ldg(hp1 + kc + 4);

        uint32_t ah[4], al[4];
        ah[0] = f32_to_tf32(a0); al[0] = f32_to_tf32(a0 - __uint_as_float(ah[0]));
        ah[1] = f32_to_tf32(a1); al[1] = f32_to_tf32(a1 - __uint_as_float(ah[1]));
        ah[2] = f32_to_tf32(a2); al[2] = f32_to_tf32(a2 - __uint_as_float(ah[2]));
        ah[3] = f32_to_tf32(a3); al[3] = f32_to_tf32(a3 - __uint_as_float(ah[3]));

        const float4* wp = sB + j * 32 + lane;
#pragma unroll
        for (int t = 0; t < 8; t++) {
            float4 bf = wp[t * 512];        // lds.128, conflict-free
            uint32_t bh0 = __float_as_uint(bf.x);
            uint32_t bh1 = __float_as_uint(bf.y);
            uint32_t bl0 = __float_as_uint(bf.z);
            uint32_t bl1 = __float_as_uint(bf.w);
            mma_tf32(acc[t], ah, bh0, bh1);   // Ah*Bh
            mma_tf32(acc[t], ah, bl0, bl1);   // Ah*Bl
            mma_tf32(acc[t], al, bh0, bh1);   // Al*Bh
        }
    }

    // epilogue
#pragma unroll
    for (int t = 0; t < 8; t++) {
        int col = half * 64 + t * 8 + (lane & 3) * 2;
        float b0 = __ldg(bias + col);
        float b1 = __ldg(bias + col + 1);
        if (rowA0 < N_NODES) {
            float2 v = make_float2(acc[t][0] + b0, acc[t][1] + b1);
            *reinterpret_cast<float2*>(out + (size_t)rowA0 * D + col) = v;
        }
        if (rowA1 < N_NODES) {
            float2 v = make_float2(acc[t][2] + b0, acc[t][3] + b1);
            *reinterpret_cast<float2*>(out + (size_t)rowA1 * D + col) = v;
        }
    }
}

// ---------------------------------------------------------------------------
// Launch: inputs in metadata order: x, src, dst, W, b
// ---------------------------------------------------------------------------
extern "C" void kernel_launch(void* const* d_in, const int* in_sizes, int n_in,
                              void* d_out, int out_size) {
    const float* x   = (const float*)d_in[0];
    const int*   src = (const int*)d_in[1];
    const int*   dst = (const int*)d_in[2];
    const float* W   = (const float*)d_in[3];
    const float* b   = (const float*)d_in[4];
    float* out = (float*)d_out;

    const int n_edges = in_sizes[1];

    // 1) fused init: zero g_h + pack W
    init_kernel<<<ZERO_BLOCKS + PACK_BLOCKS, 256>>>(W);

    // 2) scatter-add edges (one warp per edge)
    {
        long long total_threads = (long long)n_edges * 32;
        int blocks = (int)((total_threads + 255) / 256);
        scatter_edges_kernel<<<blocks, 256>>>(x, src, dst, n_edges);
    }

    // 3) tensor-core GEMM + bias (tf32x3), smem-staged B
    {
        static bool attr_set = false;
        if (!attr_set) {
            cudaFuncSetAttribute(gemm_mma_kernel,
                                 cudaFuncAttributeMaxDynamicSharedMemorySize,
                                 SB_ELEMS * sizeof(float4));
            attr_set = true;
        }
        dim3 grid(N_TILES, 2);
        gemm_mma_kernel<<<grid, 256, SB_ELEMS * sizeof(float4)>>>(b, out);
    }
}

// round 7
// speedup vs baseline: 1.4862x; 1.0587x over previous
#include <cuda_runtime.h>
#include <cstdint>

#define N_NODES 50000
#define D 128
#define N_TILES ((N_NODES + 127) / 128)   // 391
#define ZERO_BLOCKS ((N_NODES * D / 4 + 255) / 256)   // 6250
#define PACK_BLOCKS 32                                // 8192 threads

// ---------------------------------------------------------------------------
// Device scratch
// ---------------------------------------------------------------------------
__device__ float g_h[(size_t)N_NODES * D];
// W packed in k-permuted mma B-fragment order:
// [ntile t(16)][jj(8)][h(2)][lane(32)] x float4 {bhi_k0, bhi_k1, blo_k0, blo_k1}
//   n  = t*8 + (lane>>2)
//   k0 = jj*16 + (lane&3)*4 + h*2,  k1 = k0 + 1
__device__ float4 g_Wpack[16 * 8 * 2 * 32];

// ---------------------------------------------------------------------------
// tf32 helpers (plain sm_103 ISA — no 'a' features)
// ---------------------------------------------------------------------------
__device__ __forceinline__ uint32_t f32_to_tf32(float v) {
    uint32_t r;
    asm("cvt.rna.tf32.f32 %0, %1;" : "=r"(r) : "f"(v));
    return r;
}

__device__ __forceinline__ void mma_tf32(float* acc,
                                         uint32_t a0, uint32_t a1,
                                         uint32_t a2, uint32_t a3,
                                         uint32_t b0, uint32_t b1) {
    asm volatile(
        "mma.sync.aligned.m16n8k8.row.col.f32.tf32.tf32.f32 "
        "{%0,%1,%2,%3}, {%4,%5,%6,%7}, {%8,%9}, {%0,%1,%2,%3};"
        : "+f"(acc[0]), "+f"(acc[1]), "+f"(acc[2]), "+f"(acc[3])
        : "r"(a0), "r"(a1), "r"(a2), "r"(a3), "r"(b0), "r"(b1));
}

// ---------------------------------------------------------------------------
// Kernel 1: fused init — zero g_h AND pack W (k-permuted fragment order).
// ---------------------------------------------------------------------------
__global__ void init_kernel(const float* __restrict__ W) {
    int bid = blockIdx.x;
    if (bid < ZERO_BLOCKS) {
        int i = bid * 256 + threadIdx.x;
        const int n4 = N_NODES * D / 4;
        if (i < n4) reinterpret_cast<float4*>(g_h)[i] = make_float4(0.f, 0.f, 0.f, 0.f);
        return;
    }
    int idx = (bid - ZERO_BLOCKS) * 256 + threadIdx.x;   // 0..8191
    if (idx >= 16 * 8 * 2 * 32) return;
    int lane = idx & 31;
    int h = (idx >> 5) & 1;
    int jj = (idx >> 6) & 7;
    int t = idx >> 9;
    int n = t * 8 + (lane >> 2);
    int k0 = jj * 16 + (lane & 3) * 4 + h * 2;

    float w0 = __ldg(W + n * D + k0);
    float w1 = __ldg(W + n * D + k0 + 1);
    uint32_t h0 = f32_to_tf32(w0);
    uint32_t h1 = f32_to_tf32(w1);
    uint32_t l0 = f32_to_tf32(w0 - __uint_as_float(h0));
    uint32_t l1 = f32_to_tf32(w1 - __uint_as_float(h1));

    float4 v;
    v.x = __uint_as_float(h0);
    v.y = __uint_as_float(h1);
    v.z = __uint_as_float(l0);
    v.w = __uint_as_float(l1);
    g_Wpack[idx] = v;
}

// ---------------------------------------------------------------------------
// Kernel 2: edge scatter — one warp per edge, red.global.add.v4.f32
// (measured at the LTS/REDG floor; unchanged)
// ---------------------------------------------------------------------------
__global__ void scatter_edges_kernel(const float* __restrict__ x,
                                     const int* __restrict__ src,
                                     const int* __restrict__ dst,
                                     int n_edges) {
    int gw = (blockIdx.x * blockDim.x + threadIdx.x) >> 5;
    int lane = threadIdx.x & 31;
    if (gw >= n_edges) return;

    int s = __ldg(src + gw);
    int d = __ldg(dst + gw);

    float4 v = __ldg(reinterpret_cast<const float4*>(x + (size_t)s * D) + lane);

    float* hp = g_h + (size_t)d * D + lane * 4;
    asm volatile("red.global.add.v4.f32 [%0], {%1, %2, %3, %4};"
                 :: "l"(hp), "f"(v.x), "f"(v.y), "f"(v.z), "f"(v.w)
                 : "memory");
}

// ---------------------------------------------------------------------------
// Kernel 3: out = h @ W^T + b via mma.sync tf32x3, k-permuted fragments.
// One warp per 16 rows x 64 cols; blockIdx.y = column half.
// A: thread (r,q) loads ONE float4 per row per jj (16 LDG.128/warp-tile,
//    full-sector, 8 lines each) — replaces 64 scalar LDG.32 x 8 lines.
// B: staged once per block in 64KB smem, conflict-free lds.128.
// ---------------------------------------------------------------------------
#define SB_ELEMS (8 * 8 * 2 * 32)          // 4096 float4 = 64KB per column half

__global__ __launch_bounds__(256, 2) void gemm_mma_kernel(
    const float* __restrict__ bias,
    float* __restrict__ out) {

    extern __shared__ float4 sB[];         // [tt(8)][jj(8)][h(2)][lane(32)]

    const int tid = threadIdx.x;
    const int wid = tid >> 5;
    const int lane = tid & 31;
    const int q = lane & 3;
    const int half = blockIdx.y;           // 0 or 1: cols [0,64) or [64,128)

    // cooperative copy of this half's B fragments (contiguous 64KB)
    {
        const float4* wsrc = g_Wpack + half * SB_ELEMS;
#pragma unroll
        for (int i = 0; i < SB_ELEMS / 256; i++)
            sB[i * 256 + tid] = __ldg(wsrc + i * 256 + tid);
    }

    const int r0 = blockIdx.x * 128 + wid * 16;
    const int rowA0 = r0 + (lane >> 2);
    const int rowA1 = rowA0 + 8;
    const int rc0 = rowA0 < N_NODES ? rowA0 : N_NODES - 1;
    const int rc1 = rowA1 < N_NODES ? rowA1 : N_NODES - 1;
    // float4 row pointers, offset by this thread's q-chunk
    const float4* hp0 = reinterpret_cast<const float4*>(g_h + (size_t)rc0 * D) + q;
    const float4* hp1 = reinterpret_cast<const float4*>(g_h + (size_t)rc1 * D) + q;

    float acc[8][4];
#pragma unroll
    for (int t = 0; t < 8; t++)
#pragma unroll
        for (int c = 0; c < 4; c++) acc[t][c] = 0.f;

    __syncthreads();

#pragma unroll
    for (int jj = 0; jj < 8; jj++) {
        // one float4 per row: physical k = jj*16 + q*4 + {0,1,2,3}
        float4 vlo = __ldg(hp0 + jj * 4);
        float4 vhi = __ldg(hp1 + jj * 4);

        uint32_t ah0[4], al0[4], ah1[4], al1[4];
        {
            const float* f0 = reinterpret_cast<const float*>(&vlo);
            const float* f1 = reinterpret_cast<const float*>(&vhi);
#pragma unroll
            for (int c = 0; c < 4; c++) {
                ah0[c] = f32_to_tf32(f0[c]);
                al0[c] = f32_to_tf32(f0[c] - __uint_as_float(ah0[c]));
                ah1[c] = f32_to_tf32(f1[c]);
                al1[c] = f32_to_tf32(f1[c] - __uint_as_float(ah1[c]));
            }
        }

#pragma unroll
        for (int h = 0; h < 2; h++) {
            // fragment: a0=(row,k0) a1=(row+8,k0) a2=(row,k1) a3=(row+8,k1)
            uint32_t Ah0 = ah0[2 * h], Ah1 = ah1[2 * h];
            uint32_t Ah2 = ah0[2 * h + 1], Ah3 = ah1[2 * h + 1];
            uint32_t Al0 = al0[2 * h], Al1 = al1[2 * h];
            uint32_t Al2 = al0[2 * h + 1], Al3 = al1[2 * h + 1];

            const float4* wp = sB + (jj * 2 + h) * 32 + lane;
#pragma unroll
            for (int t = 0; t < 8; t++) {
                float4 bf = wp[t * 512];   // [t][jj][h][lane], lds.128
                uint32_t bh0 = __float_as_uint(bf.x);
                uint32_t bh1 = __float_as_uint(bf.y);
                uint32_t bl0 = __float_as_uint(bf.z);
                uint32_t bl1 = __float_as_uint(bf.w);
                mma_tf32(acc[t], Ah0, Ah1, Ah2, Ah3, bh0, bh1);  // Ah*Bh
                mma_tf32(acc[t], Ah0, Ah1, Ah2, Ah3, bl0, bl1);  // Ah*Bl
                mma_tf32(acc[t], Al0, Al1, Al2, Al3, bh0, bh1);  // Al*Bh
            }
        }
    }

    // epilogue: acc[t] -> cols (t*8 + q*2, +1) rows rowA0/rowA1
#pragma unroll
    for (int t = 0; t < 8; t++) {
        int col = half * 64 + t * 8 + q * 2;
        float b0 = __ldg(bias + col);
        float b1 = __ldg(bias + col + 1);
        if (rowA0 < N_NODES) {
            float2 v = make_float2(acc[t][0] + b0, acc[t][1] + b1);
            *reinterpret_cast<float2*>(out + (size_t)rowA0 * D + col) = v;
        }
        if (rowA1 < N_NODES) {
            float2 v = make_float2(acc[t][2] + b0, acc[t][3] + b1);
            *reinterpret_cast<float2*>(out + (size_t)rowA1 * D + col) = v;
        }
    }
}

// ---------------------------------------------------------------------------
// Launch: inputs in metadata order: x, src, dst, W, b
// ---------------------------------------------------------------------------
extern "C" void kernel_launch(void* const* d_in, const int* in_sizes, int n_in,
                              void* d_out, int out_size) {
    const float* x   = (const float*)d_in[0];
    const int*   src = (const int*)d_in[1];
    const int*   dst = (const int*)d_in[2];
    const float* W   = (const float*)d_in[3];
    const float* b   = (const float*)d_in[4];
    float* out = (float*)d_out;

    const int n_edges = in_sizes[1];

    // 1) fused init: zero g_h + pack W
    init_kernel<<<ZERO_BLOCKS + PACK_BLOCKS, 256>>>(W);

    // 2) scatter-add edges (one warp per edge)
    {
        long long total_threads = (long long)n_edges * 32;
        int blocks = (int)((total_threads + 255) / 256);
        scatter_edges_kernel<<<blocks, 256>>>(x, src, dst, n_edges);
    }

    // 3) tensor-core GEMM + bias (tf32x3), vectorized A + smem B
    {
        static bool attr_set = false;
        if (!attr_set) {
            cudaFuncSetAttribute(gemm_mma_kernel,
                                 cudaFuncAttributeMaxDynamicSharedMemorySize,
                                 SB_ELEMS * sizeof(float4));
            attr_set = true;
        }
        dim3 grid(N_TILES, 2);
        gemm_mma_kernel<<<grid, 256, SB_ELEMS * sizeof(float4)>>>(b, out);
    }
}

// round 8
// speedup vs baseline: 1.6112x; 1.0841x over previous
#include <cuda_runtime.h>
#include <cstdint>

#define N_NODES 50000
#define D 128
#define N_TILES ((N_NODES + 127) / 128)   // 391
#define ZERO_BLOCKS ((N_NODES * D / 4 + 255) / 256)   // 6250
#define PACK_BLOCKS 16                                // 4096 threads

// ---------------------------------------------------------------------------
// Device scratch
// ---------------------------------------------------------------------------
__device__ float g_h[(size_t)N_NODES * D];
// W packed in k-permuted bf16 m16n8k16 B-fragment order:
// [ntile t(16)][kstep(8)][lane(32)] x float4 {bh0, bh1, bl0, bl1} (bf16x2 bits)
//   n  = t*8 + (lane>>2)
//   b0 covers k = kstep*16 + (lane&3)*4 + {0,1}   (lo,hi)
//   b1 covers k = kstep*16 + (lane&3)*4 + {2,3}
__device__ float4 g_Wpack[16 * 8 * 32];

// ---------------------------------------------------------------------------
// bf16 helpers (plain sm_103 ISA — no 'a' features)
// ---------------------------------------------------------------------------
__device__ __forceinline__ uint32_t pack_bf16x2(float lo, float hi) {
    uint32_t r;
    // cvt d, a, b  ->  d.hi = cvt(a), d.lo = cvt(b)
    asm("cvt.rn.bf16x2.f32 %0, %1, %2;" : "=r"(r) : "f"(hi), "f"(lo));
    return r;
}
__device__ __forceinline__ float bf16x2_lo_f32(uint32_t v) {
    return __uint_as_float(v << 16);
}
__device__ __forceinline__ float bf16x2_hi_f32(uint32_t v) {
    return __uint_as_float(v & 0xffff0000u);
}

__device__ __forceinline__ void mma_bf16(float* acc,
                                         uint32_t a0, uint32_t a1,
                                         uint32_t a2, uint32_t a3,
                                         uint32_t b0, uint32_t b1) {
    asm volatile(
        "mma.sync.aligned.m16n8k16.row.col.f32.bf16.bf16.f32 "
        "{%0,%1,%2,%3}, {%4,%5,%6,%7}, {%8,%9}, {%0,%1,%2,%3};"
        : "+f"(acc[0]), "+f"(acc[1]), "+f"(acc[2]), "+f"(acc[3])
        : "r"(a0), "r"(a1), "r"(a2), "r"(a3), "r"(b0), "r"(b1));
}

// ---------------------------------------------------------------------------
// Kernel 1: fused init — zero g_h AND pack W into bf16 hi/lo B fragments.
// ---------------------------------------------------------------------------
__global__ void init_kernel(const float* __restrict__ W) {
    int bid = blockIdx.x;
    if (bid < ZERO_BLOCKS) {
        int i = bid * 256 + threadIdx.x;
        const int n4 = N_NODES * D / 4;
        if (i < n4) reinterpret_cast<float4*>(g_h)[i] = make_float4(0.f, 0.f, 0.f, 0.f);
        return;
    }
    int idx = (bid - ZERO_BLOCKS) * 256 + threadIdx.x;   // 0..4095
    if (idx >= 16 * 8 * 32) return;
    int lane = idx & 31;
    int kstep = (idx >> 5) & 7;
    int t = idx >> 8;
    int n = t * 8 + (lane >> 2);
    int k0 = kstep * 16 + (lane & 3) * 4;

    float w0 = __ldg(W + n * D + k0 + 0);
    float w1 = __ldg(W + n * D + k0 + 1);
    float w2 = __ldg(W + n * D + k0 + 2);
    float w3 = __ldg(W + n * D + k0 + 3);

    uint32_t bh0 = pack_bf16x2(w0, w1);
    uint32_t bh1 = pack_bf16x2(w2, w3);
    uint32_t bl0 = pack_bf16x2(w0 - bf16x2_lo_f32(bh0), w1 - bf16x2_hi_f32(bh0));
    uint32_t bl1 = pack_bf16x2(w2 - bf16x2_lo_f32(bh1), w3 - bf16x2_hi_f32(bh1));

    float4 v;
    v.x = __uint_as_float(bh0);
    v.y = __uint_as_float(bh1);
    v.z = __uint_as_float(bl0);
    v.w = __uint_as_float(bl1);
    g_Wpack[idx] = v;
}

// ---------------------------------------------------------------------------
// Kernel 2: edge scatter — one warp per edge, red.global.add.v4.f32
// (at the LTS/REDG floor; unchanged)
// ---------------------------------------------------------------------------
__global__ void scatter_edges_kernel(const float* __restrict__ x,
                                     const int* __restrict__ src,
                                     const int* __restrict__ dst,
                                     int n_edges) {
    int gw = (blockIdx.x * blockDim.x + threadIdx.x) >> 5;
    int lane = threadIdx.x & 31;
    if (gw >= n_edges) return;

    int s = __ldg(src + gw);
    int d = __ldg(dst + gw);

    float4 v = __ldg(reinterpret_cast<const float4*>(x + (size_t)s * D) + lane);

    float* hp = g_h + (size_t)d * D + lane * 4;
    asm volatile("red.global.add.v4.f32 [%0], {%1, %2, %3, %4};"
                 :: "l"(hp), "f"(v.x), "f"(v.y), "f"(v.z), "f"(v.w)
                 : "memory");
}

// ---------------------------------------------------------------------------
// Kernel 3: out = h @ W^T + b via mma.sync bf16x3 (m16n8k16).
// One warp per 16 rows x 64 cols; blockIdx.y = column half.
// A: one LDG.128 per row-group per kstep; split into bf16 hi/lo pairs.
// B: hi+lo in ONE lds.128 per (kstep, ntile); staged once per block (32KB).
// Per warp: 192 mma + 64 lds + 16 ldg (vs tf32x3: 384 mma + 128 lds).
// ---------------------------------------------------------------------------
#define SB_ELEMS (8 * 8 * 32)              // 2048 float4 = 32KB per column half

__global__ __launch_bounds__(256, 2) void gemm_mma_kernel(
    const float* __restrict__ bias,
    float* __restrict__ out) {

    extern __shared__ float4 sB[];         // [tt(8)][kstep(8)][lane(32)]

    const int tid = threadIdx.x;
    const int wid = tid >> 5;
    const int lane = tid & 31;
    const int q = lane & 3;
    const int half = blockIdx.y;           // 0 or 1: cols [0,64) or [64,128)

    // cooperative copy of this half's B fragments (contiguous 32KB)
    {
        const float4* wsrc = g_Wpack + half * SB_ELEMS;
#pragma unroll
        for (int i = 0; i < SB_ELEMS / 256; i++)
            sB[i * 256 + tid] = __ldg(wsrc + i * 256 + tid);
    }

    const int r0 = blockIdx.x * 128 + wid * 16;
    const int rowA0 = r0 + (lane >> 2);
    const int rowA1 = rowA0 + 8;
    const int rc0 = rowA0 < N_NODES ? rowA0 : N_NODES - 1;
    const int rc1 = rowA1 < N_NODES ? rowA1 : N_NODES - 1;
    const float4* hp0 = reinterpret_cast<const float4*>(g_h + (size_t)rc0 * D) + q;
    const float4* hp1 = reinterpret_cast<const float4*>(g_h + (size_t)rc1 * D) + q;

    float acc[8][4];
#pragma unroll
    for (int t = 0; t < 8; t++)
#pragma unroll
        for (int c = 0; c < 4; c++) acc[t][c] = 0.f;

    __syncthreads();

#pragma unroll
    for (int kstep = 0; kstep < 8; kstep++) {
        // physical k = kstep*16 + q*4 + {0,1,2,3}, one float4 per row
        float4 v0 = __ldg(hp0 + kstep * 4);
        float4 v1 = __ldg(hp1 + kstep * 4);

        // hi fragments (a0: row r, k {0,1}; a1: row r+8; a2: row r, k {2,3}; a3: row r+8)
        uint32_t Ah0 = pack_bf16x2(v0.x, v0.y);
        uint32_t Ah1 = pack_bf16x2(v1.x, v1.y);
        uint32_t Ah2 = pack_bf16x2(v0.z, v0.w);
        uint32_t Ah3 = pack_bf16x2(v1.z, v1.w);
        // lo fragments = residuals
        uint32_t Al0 = pack_bf16x2(v0.x - bf16x2_lo_f32(Ah0), v0.y - bf16x2_hi_f32(Ah0));
        uint32_t Al1 = pack_bf16x2(v1.x - bf16x2_lo_f32(Ah1), v1.y - bf16x2_hi_f32(Ah1));
        uint32_t Al2 = pack_bf16x2(v0.z - bf16x2_lo_f32(Ah2), v0.w - bf16x2_hi_f32(Ah2));
        uint32_t Al3 = pack_bf16x2(v1.z - bf16x2_lo_f32(Ah3), v1.w - bf16x2_hi_f32(Ah3));

        const float4* wp = sB + kstep * 32 + lane;
#pragma unroll
        for (int t = 0; t < 8; t++) {
            float4 bf = wp[t * 256];       // [t][kstep][lane], lds.128
            uint32_t bh0 = __float_as_uint(bf.x);
            uint32_t bh1 = __float_as_uint(bf.y);
            uint32_t bl0 = __float_as_uint(bf.z);
            uint32_t bl1 = __float_as_uint(bf.w);
            mma_bf16(acc[t], Ah0, Ah1, Ah2, Ah3, bh0, bh1);  // Ah*Bh
            mma_bf16(acc[t], Ah0, Ah1, Ah2, Ah3, bl0, bl1);  // Ah*Bl
            mma_bf16(acc[t], Al0, Al1, Al2, Al3, bh0, bh1);  // Al*Bh
        }
    }

    // epilogue: acc[t] c0/c1 -> rowA0 cols (t*8+q*2, +1); c2/c3 -> rowA1
#pragma unroll
    for (int t = 0; t < 8; t++) {
        int col = half * 64 + t * 8 + q * 2;
        float b0 = __ldg(bias + col);
        float b1 = __ldg(bias + col + 1);
        if (rowA0 < N_NODES) {
            float2 v = make_float2(acc[t][0] + b0, acc[t][1] + b1);
            *reinterpret_cast<float2*>(out + (size_t)rowA0 * D + col) = v;
        }
        if (rowA1 < N_NODES) {
            float2 v = make_float2(acc[t][2] + b0, acc[t][3] + b1);
            *reinterpret_cast<float2*>(out + (size_t)rowA1 * D + col) = v;
        }
    }
}

// ---------------------------------------------------------------------------
// Launch: inputs in metadata order: x, src, dst, W, b
// ---------------------------------------------------------------------------
extern "C" void kernel_launch(void* const* d_in, const int* in_sizes, int n_in,
                              void* d_out, int out_size) {
    const float* x   = (const float*)d_in[0];
    const int*   src = (const int*)d_in[1];
    const int*   dst = (const int*)d_in[2];
    const float* W   = (const float*)d_in[3];
    const float* b   = (const float*)d_in[4];
    float* out = (float*)d_out;

    const int n_edges = in_sizes[1];

    // 1) fused init: zero g_h + pack W (bf16 hi/lo)
    init_kernel<<<ZERO_BLOCKS + PACK_BLOCKS, 256>>>(W);

    // 2) scatter-add edges (one warp per edge)
    {
        long long total_threads = (long long)n_edges * 32;
        int blocks = (int)((total_threads + 255) / 256);
        scatter_edges_kernel<<<blocks, 256>>>(x, src, dst, n_edges);
    }

    // 3) tensor-core GEMM + bias (bf16x3, m16n8k16)
    {
        static bool attr_set = false;
        if (!attr_set) {
            cudaFuncSetAttribute(gemm_mma_kernel,
                                 cudaFuncAttributeMaxDynamicSharedMemorySize,
                                 SB_ELEMS * sizeof(float4));
            attr_set = true;
        }
        dim3 grid(N_TILES, 2);
        gemm_mma_kernel<<<grid, 256, SB_ELEMS * sizeof(float4)>>>(b, out);
    }
}